// round 12
// baseline (speedup 1.0000x reference)
#include <cuda_runtime.h>
#include <cuda_fp16.h>
#include <stdint.h>

// Problem constants
#define HWv 4096
#define NPIXv 65536
#define NUMELv 4194304
#define NT 128               // codes per tile
#define NTILES 8
#define BLKPIX 128           // pixels per block (main)
#define GRIDv (NPIXv/BLKPIX) // 512 blocks
#define RBLK 256             // rescore block
#define RGRID (NPIXv/RBLK)   // 256 blocks

// Dynamic SMEM layout (main kernel, bytes)
#define SM_A   0             // 128 rows x 128B (x fp16, SW128)
#define SM_B0  16384
#define SM_B1  32768
#define SM_C2H 49152         // 1024 floats (0.5*||e||^2)
#define SM_TOTAL (49152 + 4096)

__device__ __align__(16) unsigned char g_b16[NTILES][16384];
__device__ float    g_c2h[1024];
__device__ unsigned g_cand[NPIXv];   // 3 candidate indices, 10 bits each
__device__ float    g_loss;
__device__ unsigned g_count;

static __device__ __forceinline__ uint32_t s2u(const void* p) {
    uint32_t a;
    asm("{ .reg .u64 t; cvta.to.shared.u64 t, %1; cvt.u32.u64 %0, t; }" : "=r"(a) : "l"(p));
    return a;
}
static __device__ __forceinline__ unsigned umaxu(unsigned a, unsigned b) { return a > b ? a : b; }
static __device__ __forceinline__ unsigned uminu(unsigned a, unsigned b) { return a < b ? a : b; }

#define LDSM4(R, addr) \
    asm volatile("ldmatrix.sync.aligned.m8n8.x4.shared.b16 {%0,%1,%2,%3}, [%4];" \
        : "=r"((R)[0]), "=r"((R)[1]), "=r"((R)[2]), "=r"((R)[3]) : "r"(addr))
#define MMAH(D, A, B) \
    asm volatile("mma.sync.aligned.m16n8k16.row.col.f32.f16.f16.f32 " \
        "{%0,%1,%2,%3}, {%4,%5,%6,%7}, {%8,%9}, {%0,%1,%2,%3};" \
        : "+f"((D)[0]), "+f"((D)[1]), "+f"((D)[2]), "+f"((D)[3]) \
        : "r"((A)[0]), "r"((A)[1]), "r"((A)[2]), "r"((A)[3]), "r"((B)[0]), "r"((B)[1]))

static __device__ __forceinline__ void cp16(uint32_t dst, const void* src) {
    uint64_t g;
    asm("cvta.to.global.u64 %0, %1;" : "=l"(g) : "l"(src));
    asm volatile("cp.async.cg.shared.global [%0], [%1], 16;" :: "r"(dst), "l"(g));
}

// --- Kernel 0: prepack codebook (fp16, SW128 tile image) + 0.5*||e||^2 ------
// 32 blocks x 128 threads, 4 threads per code (quarter-row each).
__global__ __launch_bounds__(128) void vq_prep(const float* __restrict__ emb) {
    const int tid  = threadIdx.x;
    const int kloc = tid >> 2;
    const int part = tid & 3;
    const int k    = blockIdx.x * 32 + kloc;
    const int t    = k >> 7;
    const int row  = k & 127;
    const float4* er = (const float4*)(emb + k * 64) + part * 4;
    unsigned char* bp = g_b16[t];
    float s0 = 0.f, s1 = 0.f, s2 = 0.f, s3 = 0.f;
    #pragma unroll
    for (int i = 0; i < 4; i++) {
        float4 v = er[i];
        s0 = __fmaf_rn(v.x, v.x, s0);
        s1 = __fmaf_rn(v.y, v.y, s1);
        s2 = __fmaf_rn(v.z, v.z, s2);
        s3 = __fmaf_rn(v.w, v.w, s3);
        __half h0 = __float2half_rn(v.x), h1 = __float2half_rn(v.y);
        __half h2 = __float2half_rn(v.z), h3 = __float2half_rn(v.w);
        uint32_t p0 = ((uint32_t)__half_as_ushort(h1) << 16) | __half_as_ushort(h0);
        uint32_t p1 = ((uint32_t)__half_as_ushort(h3) << 16) | __half_as_ushort(h2);
        const int ii = part * 4 + i;
        uint32_t o0 = (uint32_t)(row * 128 + (4 * ii) * 2);
        uint32_t o1 = (uint32_t)(row * 128 + (4 * ii + 2) * 2);
        o0 = o0 ^ ((o0 >> 3) & 0x70);
        o1 = o1 ^ ((o1 >> 3) & 0x70);
        *(uint32_t*)(bp + o0) = p0;
        *(uint32_t*)(bp + o1) = p1;
    }
    float s = __fadd_rn(__fadd_rn(s0, s1), __fadd_rn(s2, s3));
    s += __shfl_xor_sync(0xffffffffu, s, 1);
    s += __shfl_xor_sync(0xffffffffu, s, 2);
    if (part == 0) g_c2h[k] = 0.5f * s;
}

// --- Kernel 1: fp16 MMA search, top-3 candidates per pixel ------------------
__global__ __launch_bounds__(BLKPIX, 4) void vq_main(const float* __restrict__ in) {
    extern __shared__ char sm[];
    const uint32_t sb = s2u(sm);
    const int tid  = threadIdx.x;
    const int lane = tid & 31;
    const int q    = lane >> 2;
    const int qp   = lane & 3;
    const int wrow = (tid >> 5) * 32;

    // stage c2h into smem
    {
        float4* sc2 = (float4*)(sm + SM_C2H);
        const float4* gc2 = (const float4*)g_c2h;
        sc2[tid] = gc2[tid];
        sc2[tid + BLKPIX] = gc2[tid + BLKPIX];
    }
    // load x -> fp16 A tile (SW128)
    const int p0 = blockIdx.x * BLKPIX + tid;
    const int b0 = p0 >> 12, h0i = (p0 >> 6) & 63, w0 = p0 & 63;
    const float* xin = in + ((b0 * 64) * 64 + h0i) * 64 + w0;
    #pragma unroll
    for (int c = 0; c < 64; c += 2) {
        float f0 = xin[c * HWv], f1 = xin[(c + 1) * HWv];
        __half h0 = __float2half_rn(f0), h1 = __float2half_rn(f1);
        uint32_t ph = ((uint32_t)__half_as_ushort(h1) << 16) | __half_as_ushort(h0);
        uint32_t off = (uint32_t)(tid * 128 + c * 2);
        off = off ^ ((off >> 3) & 0x70);
        *(uint32_t*)(sm + SM_A + off) = ph;
    }
    // prefetch B tile 0
    #pragma unroll
    for (int j = 0; j < 8; j++)
        cp16(sb + SM_B0 + tid * 128 + j * 16, g_b16[0] + tid * 128 + j * 16);
    asm volatile("cp.async.commit_group;" ::: "memory");

    // publish A tile + c2h, then hoist ALL A fragments into registers (invariant
    // across the whole code-tile loop): 4 ks x 2 row-frags x 4 regs = 32 regs.
    __syncthreads();
    const int arow0 = wrow + (lane & 15);
    const uint32_t aswz0 = (uint32_t)((arow0 & 7) << 4);
    const uint32_t aswz1 = (uint32_t)(((arow0 + 16) & 7) << 4);
    const uint32_t abase0 = sb + SM_A + (uint32_t)(arow0 * 128);
    const uint32_t abase1 = sb + SM_A + (uint32_t)((arow0 + 16) * 128);
    uint32_t Af[4][2][4];
    #pragma unroll
    for (int ks = 0; ks < 4; ks++) {
        const uint32_t akb = (uint32_t)(ks * 32) + (uint32_t)((lane >> 4) << 4);
        LDSM4(Af[ks][0], abase0 + (akb ^ aswz0));
        LDSM4(Af[ks][1], abase1 + (akb ^ aswz1));
    }

    const int brow = (lane & 7) + ((lane >> 4) << 3);
    const uint32_t bswz = (uint32_t)((brow & 7) << 4);
    const uint32_t bkhi = (uint32_t)(((lane >> 3) & 1) * 16);
    const uint32_t browoff = (uint32_t)(brow * 128);

    unsigned t1[4] = {0,0,0,0}, t2[4] = {0,0,0,0};

    for (int t = 0; t < NTILES; t++) {
        const uint32_t bB = sb + ((t & 1) ? SM_B1 : SM_B0);
        // wait for tile t data, then one sync: publishes tile t AND proves
        // everyone is done reading buffer (t+1)&1 (consumed during iter t-1)
        asm volatile("cp.async.wait_group 0;" ::: "memory");
        __syncthreads();
        if (t < NTILES - 1) {
            const uint32_t bN = sb + ((t & 1) ? SM_B0 : SM_B1);
            #pragma unroll
            for (int j = 0; j < 8; j++)
                cp16(bN + tid * 128 + j * 16, g_b16[t + 1] + tid * 128 + j * 16);
            asm volatile("cp.async.commit_group;" ::: "memory");
        }

        #pragma unroll
        for (int quar = 0; quar < 4; quar++) {
            float acc[8][4];
            #pragma unroll
            for (int f = 0; f < 8; f++) {
                acc[f][0] = 0.f; acc[f][1] = 0.f; acc[f][2] = 0.f; acc[f][3] = 0.f;
            }
            const uint32_t bbase = bB + (uint32_t)(quar * 4096) + browoff;
            #pragma unroll
            for (int ks = 0; ks < 4; ks++) {
                const uint32_t bk = ((uint32_t)(ks * 32) + bkhi) ^ bswz;
                uint32_t Bx[8];
                LDSM4(Bx,     bbase + bk);
                LDSM4(Bx + 4, bbase + 2048 + bk);
                MMAH(acc[0], Af[ks][0], Bx + 0); MMAH(acc[1], Af[ks][1], Bx + 0);
                MMAH(acc[2], Af[ks][0], Bx + 2); MMAH(acc[3], Af[ks][1], Bx + 2);
                MMAH(acc[4], Af[ks][0], Bx + 4); MMAH(acc[5], Af[ks][1], Bx + 4);
                MMAH(acc[6], Af[ks][0], Bx + 6); MMAH(acc[7], Af[ks][1], Bx + 6);
            }
            // reduce: key = 0.5*c2 - dot; top-2 per (lane, slot), unsigned-max on raw bits
            const float* c2b = (const float*)(sm + SM_C2H) + t * 128 + quar * 32 + qp * 2;
            const unsigned ccb = 1023u - (unsigned)(t * 128 + quar * 32 + qp * 2);
            #pragma unroll
            for (int cf = 0; cf < 4; cf++) {
                float c0 = c2b[cf * 8];
                float c1 = c2b[cf * 8 + 1];
                unsigned i0 = ccb - (unsigned)(cf * 8);
                unsigned i1 = i0 - 1u;
                #pragma unroll
                for (int r = 0; r < 2; r++) {
                    #pragma unroll
                    for (int i = 0; i < 4; i++) {
                        float dk = __fsub_rn((i & 1) ? c1 : c0, acc[cf*2+r][i]);
                        unsigned km = (__float_as_uint(dk) & 0xFFFFFC00u) | ((i & 1) ? i1 : i0);
                        const int s = r * 2 + (i >> 1);
                        unsigned m1 = uminu(t1[s], km);
                        t1[s] = umaxu(t1[s], km);
                        t2[s] = umaxu(t2[s], m1);
                    }
                }
            }
        }
    }

    // merge the 4 quad-lanes' top-2 -> exact union top-3 per pixel
    unsigned t3[4] = {0,0,0,0};
    #pragma unroll
    for (int s = 0; s < 4; s++) {
        #pragma unroll
        for (int mk = 1; mk <= 2; mk <<= 1) {
            unsigned r1 = __shfl_xor_sync(0xffffffffu, t1[s], mk);
            unsigned r2 = __shfl_xor_sync(0xffffffffu, t2[s], mk);
            unsigned r3 = __shfl_xor_sync(0xffffffffu, t3[s], mk);
            unsigned x1 = umaxu(t1[s], r1), y1 = uminu(t1[s], r1);
            unsigned x2 = umaxu(t2[s], r2);
            t1[s] = x1;
            unsigned top2 = umaxu(y1, x2);
            t3[s] = umaxu(uminu(y1, x2), umaxu(t3[s], r3));
            t2[s] = top2;
        }
    }
    unsigned f1 = t1[0], f2 = t2[0], f3 = t3[0];
    if (qp == 1) { f1 = t1[1]; f2 = t2[1]; f3 = t3[1]; }
    if (qp == 2) { f1 = t1[2]; f2 = t2[2]; f3 = t3[2]; }
    if (qp == 3) { f1 = t1[3]; f2 = t2[3]; f3 = t3[3]; }

    const int p = blockIdx.x * BLKPIX + wrow + q + qp * 8;
    const unsigned k1 = 1023u - (f1 & 1023u);
    const unsigned k2 = 1023u - (f2 & 1023u);
    const unsigned k3 = 1023u - (f3 & 1023u);
    g_cand[p] = k1 | (k2 << 10) | (k3 << 20);
}

// Exact fp32 distance, replicating the verified 0-flip summation structure.
static __device__ __forceinline__ float exact_dist(const float* x, const float* __restrict__ e,
                                                   float sx) {
    const float4* e4 = (const float4*)e;
    float cc0=0,cc1=0,cc2=0,cc3=0,cc4=0,cc5=0,cc6=0,cc7=0;
    float s0=0,s1=0,s2=0,s3=0;
    #pragma unroll
    for (int i = 0; i < 16; i++) {
        float4 v = e4[i];
        s0 = __fmaf_rn(v.x, v.x, s0);
        s1 = __fmaf_rn(v.y, v.y, s1);
        s2 = __fmaf_rn(v.z, v.z, s2);
        s3 = __fmaf_rn(v.w, v.w, s3);
        float x0 = x[4*i], x1 = x[4*i+1], x2 = x[4*i+2], x3 = x[4*i+3];
        if ((i & 1) == 0) {
            cc0 = __fmaf_rn(x0, v.x, cc0); cc1 = __fmaf_rn(x1, v.y, cc1);
            cc2 = __fmaf_rn(x2, v.z, cc2); cc3 = __fmaf_rn(x3, v.w, cc3);
        } else {
            cc4 = __fmaf_rn(x0, v.x, cc4); cc5 = __fmaf_rn(x1, v.y, cc5);
            cc6 = __fmaf_rn(x2, v.z, cc6); cc7 = __fmaf_rn(x3, v.w, cc7);
        }
    }
    float c2 = __fadd_rn(__fadd_rn(s0, s1), __fadd_rn(s2, s3));
    float lo = __fadd_rn(__fadd_rn(cc0, cc2), __fadd_rn(cc4, cc6));
    float hi = __fadd_rn(__fadd_rn(cc1, cc3), __fadd_rn(cc5, cc7));
    float dot = __fadd_rn(lo, hi);
    return __fsub_rn(__fadd_rn(sx, c2), __fmul_rn(2.0f, dot));
}

// --- Kernel 2: exact rescore of 3 candidates, output + loss -----------------
__global__ __launch_bounds__(RBLK) void vq_rescore(const float* __restrict__ in,
                                                   const float* __restrict__ emb,
                                                   float* __restrict__ out,
                                                   int out_size) {
    const int tid = threadIdx.x;
    const int p = blockIdx.x * RBLK + tid;
    const int b = p >> 12, h = (p >> 6) & 63, w = p & 63;
    const unsigned cand = g_cand[p];
    const int k1 = (int)(cand & 1023u);
    const int k2 = (int)((cand >> 10) & 1023u);
    const int k3 = (int)((cand >> 20) & 1023u);

    const float* xg = in + ((b * 64) * 64 + h) * 64 + w;
    float x_[64];
    #pragma unroll
    for (int c = 0; c < 64; c++) x_[c] = xg[c * HWv];
    float s0 = 0.f, s1 = 0.f, s2 = 0.f, s3 = 0.f;
    #pragma unroll
    for (int i = 0; i < 32; i++) {
        float f0v = x_[2*i], f1v = x_[2*i + 1];
        if (i & 1) { s1 = __fmaf_rn(f0v, f0v, s1); s3 = __fmaf_rn(f1v, f1v, s3); }
        else       { s0 = __fmaf_rn(f0v, f0v, s0); s2 = __fmaf_rn(f1v, f1v, s2); }
    }
    const float sx = __fadd_rn(__fadd_rn(s0, s1), __fadd_rn(s2, s3));
    const float d1 = exact_dist(x_, emb + k1 * 64, sx);
    const float d2 = exact_dist(x_, emb + k2 * 64, sx);
    const float d3 = exact_dist(x_, emb + k3 * 64, sx);
    float db = d1; int kwin = k1;
    if (d2 < db || (d2 == db && k2 < kwin)) { db = d2; kwin = k2; }
    if (d3 < db || (d3 == db && k3 < kwin)) { db = d3; kwin = k3; }

    const float4* eb = (const float4*)(emb + kwin * 64);
    float* op = out + ((b * 64) * 64 + h) * 64 + w;
    float ls = 0.f;
    #pragma unroll
    for (int i = 0; i < 16; i++) {
        float4 qv = eb[i];
        op[(4*i + 0) * HWv] = qv.x;
        op[(4*i + 1) * HWv] = qv.y;
        op[(4*i + 2) * HWv] = qv.z;
        op[(4*i + 3) * HWv] = qv.w;
        float e0 = qv.x - x_[4*i],   e1 = qv.y - x_[4*i+1];
        float e2 = qv.z - x_[4*i+2], e3 = qv.w - x_[4*i+3];
        ls += e0*e0 + e1*e1 + e2*e2 + e3*e3;
    }
    #pragma unroll
    for (int off = 16; off; off >>= 1)
        ls += __shfl_xor_sync(0xffffffffu, ls, off);
    if ((tid & 31) == 0) atomicAdd(&g_loss, ls);

    __syncthreads();
    if (tid == 0) {
        __threadfence();
        unsigned v = atomicAdd(&g_count, 1u);
        if (v == RGRID - 1) {
            __threadfence();
            if (out_size > NUMELv)
                out[NUMELv] = 1.25f * g_loss / (float)NUMELv;
            g_loss = 0.f;
            g_count = 0u;
        }
    }
}

extern "C" void kernel_launch(void* const* d_in, const int* in_sizes, int n_in,
                              void* d_out, int out_size) {
    const float* in  = (const float*)d_in[0];
    const float* emb = (const float*)d_in[1];
    float* out = (float*)d_out;

    vq_prep<<<32, 128>>>(emb);
    cudaFuncSetAttribute(vq_main, cudaFuncAttributeMaxDynamicSharedMemorySize, SM_TOTAL);
    vq_main<<<GRIDv, BLKPIX, SM_TOTAL>>>(in);
    vq_rescore<<<RGRID, RBLK>>>(in, emb, out, out_size);
}

// round 15
// speedup vs baseline: 1.0228x; 1.0228x over previous
#include <cuda_runtime.h>
#include <cuda_fp16.h>
#include <stdint.h>

// Problem constants
#define HWv 4096
#define NPIXv 65536
#define NUMELv 4194304
#define NT 128               // codes per tile
#define NTILES 8
#define BLKPIX 128           // pixels per block (main)
#define GRIDv (NPIXv/BLKPIX) // 512 blocks
#define RBLK 256             // rescore block
#define RGRID (NPIXv/RBLK)   // 256 blocks

// Dynamic SMEM layout (main kernel, bytes)
#define SM_A   0             // 128 rows x 128B (x fp16, SW128)
#define SM_B0  16384
#define SM_B1  32768
#define SM_C2H 49152         // 1024 floats (0.5*||e||^2)
#define SM_TOTAL (49152 + 4096)

// Prepacked NEGATED codebook (-e, fp16, SW128 tile image): MMA accumulates -dot.
__device__ __align__(16) unsigned char g_b16[NTILES][16384];
__device__ float    g_c2h[1024];
__device__ unsigned g_cand[NPIXv];   // 3 candidate indices, 10 bits each
__device__ float    g_loss;
__device__ unsigned g_count;

static __device__ __forceinline__ uint32_t s2u(const void* p) {
    uint32_t a;
    asm("{ .reg .u64 t; cvta.to.shared.u64 t, %1; cvt.u32.u64 %0, t; }" : "=r"(a) : "l"(p));
    return a;
}
static __device__ __forceinline__ unsigned umaxu(unsigned a, unsigned b) { return a > b ? a : b; }
static __device__ __forceinline__ unsigned uminu(unsigned a, unsigned b) { return a < b ? a : b; }

#define LDSM4(R, addr) \
    asm volatile("ldmatrix.sync.aligned.m8n8.x4.shared.b16 {%0,%1,%2,%3}, [%4];" \
        : "=r"((R)[0]), "=r"((R)[1]), "=r"((R)[2]), "=r"((R)[3]) : "r"(addr))
#define MMAH(D, A, B) \
    asm volatile("mma.sync.aligned.m16n8k16.row.col.f32.f16.f16.f32 " \
        "{%0,%1,%2,%3}, {%4,%5,%6,%7}, {%8,%9}, {%0,%1,%2,%3};" \
        : "+f"((D)[0]), "+f"((D)[1]), "+f"((D)[2]), "+f"((D)[3]) \
        : "r"((A)[0]), "r"((A)[1]), "r"((A)[2]), "r"((A)[3]), "r"((B)[0]), "r"((B)[1]))

static __device__ __forceinline__ void cp16(uint32_t dst, const void* src) {
    uint64_t g;
    asm("cvta.to.global.u64 %0, %1;" : "=l"(g) : "l"(src));
    asm volatile("cp.async.cg.shared.global [%0], [%1], 16;" :: "r"(dst), "l"(g));
}

// --- Kernel 0: prepack NEGATED codebook (fp16, SW128) + 0.5*||e||^2 ---------
// 32 blocks x 128 threads, 4 threads per code (quarter-row each).
__global__ __launch_bounds__(128) void vq_prep(const float* __restrict__ emb) {
    const int tid  = threadIdx.x;
    const int kloc = tid >> 2;
    const int part = tid & 3;
    const int k    = blockIdx.x * 32 + kloc;
    const int t    = k >> 7;
    const int row  = k & 127;
    const float4* er = (const float4*)(emb + k * 64) + part * 4;
    unsigned char* bp = g_b16[t];
    float s0 = 0.f, s1 = 0.f, s2 = 0.f, s3 = 0.f;
    #pragma unroll
    for (int i = 0; i < 4; i++) {
        float4 v = er[i];
        s0 = __fmaf_rn(v.x, v.x, s0);
        s1 = __fmaf_rn(v.y, v.y, s1);
        s2 = __fmaf_rn(v.z, v.z, s2);
        s3 = __fmaf_rn(v.w, v.w, s3);
        __half h0 = __float2half_rn(-v.x), h1 = __float2half_rn(-v.y);
        __half h2 = __float2half_rn(-v.z), h3 = __float2half_rn(-v.w);
        uint32_t p0 = ((uint32_t)__half_as_ushort(h1) << 16) | __half_as_ushort(h0);
        uint32_t p1 = ((uint32_t)__half_as_ushort(h3) << 16) | __half_as_ushort(h2);
        const int ii = part * 4 + i;
        uint32_t o0 = (uint32_t)(row * 128 + (4 * ii) * 2);
        uint32_t o1 = (uint32_t)(row * 128 + (4 * ii + 2) * 2);
        o0 = o0 ^ ((o0 >> 3) & 0x70);
        o1 = o1 ^ ((o1 >> 3) & 0x70);
        *(uint32_t*)(bp + o0) = p0;
        *(uint32_t*)(bp + o1) = p1;
    }
    float s = __fadd_rn(__fadd_rn(s0, s1), __fadd_rn(s2, s3));
    s += __shfl_xor_sync(0xffffffffu, s, 1);
    s += __shfl_xor_sync(0xffffffffu, s, 2);
    if (part == 0) g_c2h[k] = 0.5f * s;
}

// --- Kernel 1: fp16 MMA search, top-3 candidates per pixel ------------------
// acc seeded with 0.5*c2, codebook negated => acc = 0.5*c2 - dot = key.
__global__ __launch_bounds__(BLKPIX, 4) void vq_main(const float* __restrict__ in) {
    extern __shared__ char sm[];
    const uint32_t sb = s2u(sm);
    const int tid  = threadIdx.x;
    const int lane = tid & 31;
    const int q    = lane >> 2;
    const int qp   = lane & 3;
    const int wrow = (tid >> 5) * 32;

    // stage c2h into smem
    {
        float4* sc2 = (float4*)(sm + SM_C2H);
        const float4* gc2 = (const float4*)g_c2h;
        sc2[tid] = gc2[tid];
        sc2[tid + BLKPIX] = gc2[tid + BLKPIX];
    }
    // load x -> fp16 A tile (SW128)
    const int p0 = blockIdx.x * BLKPIX + tid;
    const int b0 = p0 >> 12, h0i = (p0 >> 6) & 63, w0 = p0 & 63;
    const float* xin = in + ((b0 * 64) * 64 + h0i) * 64 + w0;
    #pragma unroll
    for (int c = 0; c < 64; c += 2) {
        float f0 = xin[c * HWv], f1 = xin[(c + 1) * HWv];
        __half h0 = __float2half_rn(f0), h1 = __float2half_rn(f1);
        uint32_t ph = ((uint32_t)__half_as_ushort(h1) << 16) | __half_as_ushort(h0);
        uint32_t off = (uint32_t)(tid * 128 + c * 2);
        off = off ^ ((off >> 3) & 0x70);
        *(uint32_t*)(sm + SM_A + off) = ph;
    }
    // prefetch B tile 0
    #pragma unroll
    for (int j = 0; j < 8; j++)
        cp16(sb + SM_B0 + tid * 128 + j * 16, g_b16[0] + tid * 128 + j * 16);
    asm volatile("cp.async.commit_group;" ::: "memory");

    // Precompute per-thread swizzled address pieces.
    const int arow0 = wrow + (lane & 15);
    const uint32_t aswz0 = (uint32_t)((arow0 & 7) << 4);
    const uint32_t aswz1 = (uint32_t)(((arow0 + 16) & 7) << 4);
    const uint32_t abase0 = sb + SM_A + (uint32_t)(arow0 * 128);
    const uint32_t abase1 = sb + SM_A + (uint32_t)((arow0 + 16) * 128);
    const int brow = (lane & 7) + ((lane >> 4) << 3);
    const uint32_t bswz = (uint32_t)((brow & 7) << 4);
    const uint32_t bkhi = (uint32_t)(((lane >> 3) & 1) * 16);
    const uint32_t browoff = (uint32_t)(brow * 128);

    unsigned t1[4] = {0,0,0,0}, t2[4] = {0,0,0,0};

    for (int t = 0; t < NTILES; t++) {
        const uint32_t bB = sb + ((t & 1) ? SM_B1 : SM_B0);
        // wait for tile t data, then one sync: publishes tile t AND proves
        // everyone is done reading buffer (t+1)&1 (consumed during iter t-1)
        asm volatile("cp.async.wait_group 0;" ::: "memory");
        __syncthreads();
        if (t < NTILES - 1) {
            const uint32_t bN = sb + ((t & 1) ? SM_B0 : SM_B1);
            #pragma unroll
            for (int j = 0; j < 8; j++)
                cp16(bN + tid * 128 + j * 16, g_b16[t + 1] + tid * 128 + j * 16);
            asm volatile("cp.async.commit_group;" ::: "memory");
        }

        #pragma unroll
        for (int half = 0; half < 2; half++) {
            const float* c2b = (const float*)(sm + SM_C2H) + t * 128 + half * 64 + qp * 2;
            // seed accumulators with 0.5*c2 of their code pair
            float acc[16][4];
            #pragma unroll
            for (int cf = 0; cf < 8; cf++) {
                float2 cc = *(const float2*)(c2b + cf * 8);
                acc[cf*2+0][0] = cc.x; acc[cf*2+0][1] = cc.y;
                acc[cf*2+0][2] = cc.x; acc[cf*2+0][3] = cc.y;
                acc[cf*2+1][0] = cc.x; acc[cf*2+1][1] = cc.y;
                acc[cf*2+1][2] = cc.x; acc[cf*2+1][3] = cc.y;
            }
            const uint32_t bbase = bB + (uint32_t)(half * 8192) + browoff;
            const int akhi = (lane >> 4) << 4;
            #pragma unroll
            for (int ks = 0; ks < 4; ks++) {
                const uint32_t akb = (uint32_t)(ks * 32) + (uint32_t)akhi;
                uint32_t A0[4], A1[4], Bx[8];
                LDSM4(A0, abase0 + (akb ^ aswz0));
                LDSM4(A1, abase1 + (akb ^ aswz1));
                const uint32_t bk = ((uint32_t)(ks * 32) + bkhi) ^ bswz;
                LDSM4(Bx,     bbase + bk);
                LDSM4(Bx + 4, bbase + 2048 + bk);
                MMAH(acc[0], A0, Bx + 0); MMAH(acc[1], A1, Bx + 0);
                MMAH(acc[2], A0, Bx + 2); MMAH(acc[3], A1, Bx + 2);
                MMAH(acc[4], A0, Bx + 4); MMAH(acc[5], A1, Bx + 4);
                MMAH(acc[6], A0, Bx + 6); MMAH(acc[7], A1, Bx + 6);
                uint32_t By[8];
                LDSM4(By,     bbase + 4096 + bk);
                LDSM4(By + 4, bbase + 6144 + bk);
                MMAH(acc[8],  A0, By + 0); MMAH(acc[9],  A1, By + 0);
                MMAH(acc[10], A0, By + 2); MMAH(acc[11], A1, By + 2);
                MMAH(acc[12], A0, By + 4); MMAH(acc[13], A1, By + 4);
                MMAH(acc[14], A0, By + 6); MMAH(acc[15], A1, By + 6);
            }
            // reduce: acc IS the key; top-2 per (lane, slot), unsigned-max on raw bits
            const unsigned ccb = 1023u - (unsigned)(t * 128 + half * 64 + qp * 2);
            #pragma unroll
            for (int cf = 0; cf < 8; cf++) {
                unsigned i0 = ccb - (unsigned)(cf * 8);
                unsigned i1 = i0 - 1u;
                #pragma unroll
                for (int r = 0; r < 2; r++) {
                    #pragma unroll
                    for (int i = 0; i < 4; i++) {
                        unsigned km = (__float_as_uint(acc[cf*2+r][i]) & 0xFFFFFC00u)
                                      | ((i & 1) ? i1 : i0);
                        const int s = r * 2 + (i >> 1);
                        unsigned m1 = uminu(t1[s], km);
                        t1[s] = umaxu(t1[s], km);
                        t2[s] = umaxu(t2[s], m1);
                    }
                }
            }
        }
    }

    // merge the 4 quad-lanes' top-2 -> exact union top-3 per pixel
    unsigned t3[4] = {0,0,0,0};
    #pragma unroll
    for (int s = 0; s < 4; s++) {
        #pragma unroll
        for (int mk = 1; mk <= 2; mk <<= 1) {
            unsigned r1 = __shfl_xor_sync(0xffffffffu, t1[s], mk);
            unsigned r2 = __shfl_xor_sync(0xffffffffu, t2[s], mk);
            unsigned r3 = __shfl_xor_sync(0xffffffffu, t3[s], mk);
            unsigned x1 = umaxu(t1[s], r1), y1 = uminu(t1[s], r1);
            unsigned x2 = umaxu(t2[s], r2);
            t1[s] = x1;
            unsigned top2 = umaxu(y1, x2);
            t3[s] = umaxu(uminu(y1, x2), umaxu(t3[s], r3));
            t2[s] = top2;
        }
    }
    unsigned f1 = t1[0], f2 = t2[0], f3 = t3[0];
    if (qp == 1) { f1 = t1[1]; f2 = t2[1]; f3 = t3[1]; }
    if (qp == 2) { f1 = t1[2]; f2 = t2[2]; f3 = t3[2]; }
    if (qp == 3) { f1 = t1[3]; f2 = t2[3]; f3 = t3[3]; }

    const int p = blockIdx.x * BLKPIX + wrow + q + qp * 8;
    const unsigned k1 = 1023u - (f1 & 1023u);
    const unsigned k2 = 1023u - (f2 & 1023u);
    const unsigned k3 = 1023u - (f3 & 1023u);
    g_cand[p] = k1 | (k2 << 10) | (k3 << 20);
}

// Exact fp32 distance, replicating the verified 0-flip summation structure.
static __device__ __forceinline__ float exact_dist(const float* x, const float* __restrict__ e,
                                                   float sx) {
    const float4* e4 = (const float4*)e;
    float cc0=0,cc1=0,cc2=0,cc3=0,cc4=0,cc5=0,cc6=0,cc7=0;
    float s0=0,s1=0,s2=0,s3=0;
    #pragma unroll
    for (int i = 0; i < 16; i++) {
        float4 v = e4[i];
        s0 = __fmaf_rn(v.x, v.x, s0);
        s1 = __fmaf_rn(v.y, v.y, s1);
        s2 = __fmaf_rn(v.z, v.z, s2);
        s3 = __fmaf_rn(v.w, v.w, s3);
        float x0 = x[4*i], x1 = x[4*i+1], x2 = x[4*i+2], x3 = x[4*i+3];
        if ((i & 1) == 0) {
            cc0 = __fmaf_rn(x0, v.x, cc0); cc1 = __fmaf_rn(x1, v.y, cc1);
            cc2 = __fmaf_rn(x2, v.z, cc2); cc3 = __fmaf_rn(x3, v.w, cc3);
        } else {
            cc4 = __fmaf_rn(x0, v.x, cc4); cc5 = __fmaf_rn(x1, v.y, cc5);
            cc6 = __fmaf_rn(x2, v.z, cc6); cc7 = __fmaf_rn(x3, v.w, cc7);
        }
    }
    float c2 = __fadd_rn(__fadd_rn(s0, s1), __fadd_rn(s2, s3));
    float lo = __fadd_rn(__fadd_rn(cc0, cc2), __fadd_rn(cc4, cc6));
    float hi = __fadd_rn(__fadd_rn(cc1, cc3), __fadd_rn(cc5, cc7));
    float dot = __fadd_rn(lo, hi);
    return __fsub_rn(__fadd_rn(sx, c2), __fmul_rn(2.0f, dot));
}

// --- Kernel 2: exact rescore of 3 candidates, output + loss -----------------
__global__ __launch_bounds__(RBLK) void vq_rescore(const float* __restrict__ in,
                                                   const float* __restrict__ emb,
                                                   float* __restrict__ out,
                                                   int out_size) {
    const int tid = threadIdx.x;
    const int p = blockIdx.x * RBLK + tid;
    const int b = p >> 12, h = (p >> 6) & 63, w = p & 63;
    const unsigned cand = g_cand[p];
    const int k1 = (int)(cand & 1023u);
    const int k2 = (int)((cand >> 10) & 1023u);
    const int k3 = (int)((cand >> 20) & 1023u);

    const float* xg = in + ((b * 64) * 64 + h) * 64 + w;
    float x_[64];
    #pragma unroll
    for (int c = 0; c < 64; c++) x_[c] = xg[c * HWv];
    float s0 = 0.f, s1 = 0.f, s2 = 0.f, s3 = 0.f;
    #pragma unroll
    for (int i = 0; i < 32; i++) {
        float f0v = x_[2*i], f1v = x_[2*i + 1];
        if (i & 1) { s1 = __fmaf_rn(f0v, f0v, s1); s3 = __fmaf_rn(f1v, f1v, s3); }
        else       { s0 = __fmaf_rn(f0v, f0v, s0); s2 = __fmaf_rn(f1v, f1v, s2); }
    }
    const float sx = __fadd_rn(__fadd_rn(s0, s1), __fadd_rn(s2, s3));
    const float d1 = exact_dist(x_, emb + k1 * 64, sx);
    const float d2 = exact_dist(x_, emb + k2 * 64, sx);
    const float d3 = exact_dist(x_, emb + k3 * 64, sx);
    float db = d1; int kwin = k1;
    if (d2 < db || (d2 == db && k2 < kwin)) { db = d2; kwin = k2; }
    if (d3 < db || (d3 == db && k3 < kwin)) { db = d3; kwin = k3; }

    const float4* eb = (const float4*)(emb + kwin * 64);
    float* op = out + ((b * 64) * 64 + h) * 64 + w;
    float ls = 0.f;
    #pragma unroll
    for (int i = 0; i < 16; i++) {
        float4 qv = eb[i];
        op[(4*i + 0) * HWv] = qv.x;
        op[(4*i + 1) * HWv] = qv.y;
        op[(4*i + 2) * HWv] = qv.z;
        op[(4*i + 3) * HWv] = qv.w;
        float e0 = qv.x - x_[4*i],   e1 = qv.y - x_[4*i+1];
        float e2 = qv.z - x_[4*i+2], e3 = qv.w - x_[4*i+3];
        ls += e0*e0 + e1*e1 + e2*e2 + e3*e3;
    }
    #pragma unroll
    for (int off = 16; off; off >>= 1)
        ls += __shfl_xor_sync(0xffffffffu, ls, off);
    if ((tid & 31) == 0) atomicAdd(&g_loss, ls);

    __syncthreads();
    if (tid == 0) {
        __threadfence();
        unsigned v = atomicAdd(&g_count, 1u);
        if (v == RGRID - 1) {
            __threadfence();
            if (out_size > NUMELv)
                out[NUMELv] = 1.25f * g_loss / (float)NUMELv;
            g_loss = 0.f;
            g_count = 0u;
        }
    }
}

extern "C" void kernel_launch(void* const* d_in, const int* in_sizes, int n_in,
                              void* d_out, int out_size) {
    const float* in  = (const float*)d_in[0];
    const float* emb = (const float*)d_in[1];
    float* out = (float*)d_out;

    vq_prep<<<32, 128>>>(emb);
    cudaFuncSetAttribute(vq_main, cudaFuncAttributeMaxDynamicSharedMemorySize, SM_TOTAL);
    vq_main<<<GRIDv, BLKPIX, SM_TOTAL>>>(in);
    vq_rescore<<<RGRID, RBLK>>>(in, emb, out, out_size);
}

// round 16
// speedup vs baseline: 1.1095x; 1.0848x over previous
#include <cuda_runtime.h>
#include <cuda_fp16.h>
#include <stdint.h>

// Problem constants
#define HWv 4096
#define NPIXv 65536
#define NUMELv 4194304
#define NT 64                // codes per tile
#define NTILES 16
#define BLKPIX 128           // pixels per block (main)
#define GRIDv (NPIXv/BLKPIX) // 512 blocks
#define RBLK 256             // rescore block
#define RGRID (NPIXv/RBLK)   // 256 blocks

// Dynamic SMEM layout (main kernel, bytes)
#define SM_A   0             // 128 rows x 128B (x fp16, SW128)
#define SM_B0  16384         // 64 rows x 128B
#define SM_B1  24576
#define SM_C2H 32768         // 1024 floats (0.5*||e||^2)
#define SM_TOTAL 36864       // x6 CTAs = 221184 <= 228KB/SM

// Prepacked NEGATED codebook (-e, fp16, SW128 tile image): MMA accumulates -dot.
__device__ __align__(16) unsigned char g_b16[NTILES][8192];
__device__ float    g_c2h[1024];
__device__ unsigned g_cand[NPIXv];   // 3 candidate indices, 10 bits each
__device__ float    g_loss;
__device__ unsigned g_count;

static __device__ __forceinline__ uint32_t s2u(const void* p) {
    uint32_t a;
    asm("{ .reg .u64 t; cvta.to.shared.u64 t, %1; cvt.u32.u64 %0, t; }" : "=r"(a) : "l"(p));
    return a;
}
static __device__ __forceinline__ unsigned umaxu(unsigned a, unsigned b) { return a > b ? a : b; }
static __device__ __forceinline__ unsigned uminu(unsigned a, unsigned b) { return a < b ? a : b; }

#define LDSM4(R, addr) \
    asm volatile("ldmatrix.sync.aligned.m8n8.x4.shared.b16 {%0,%1,%2,%3}, [%4];" \
        : "=r"((R)[0]), "=r"((R)[1]), "=r"((R)[2]), "=r"((R)[3]) : "r"(addr))
#define MMAH(D, A, B) \
    asm volatile("mma.sync.aligned.m16n8k16.row.col.f32.f16.f16.f32 " \
        "{%0,%1,%2,%3}, {%4,%5,%6,%7}, {%8,%9}, {%0,%1,%2,%3};" \
        : "+f"((D)[0]), "+f"((D)[1]), "+f"((D)[2]), "+f"((D)[3]) \
        : "r"((A)[0]), "r"((A)[1]), "r"((A)[2]), "r"((A)[3]), "r"((B)[0]), "r"((B)[1]))

static __device__ __forceinline__ void cp16(uint32_t dst, const void* src) {
    uint64_t g;
    asm("cvta.to.global.u64 %0, %1;" : "=l"(g) : "l"(src));
    asm volatile("cp.async.cg.shared.global [%0], [%1], 16;" :: "r"(dst), "l"(g));
}

// --- Kernel 0: prepack NEGATED codebook (fp16, SW128) + 0.5*||e||^2 ---------
// 32 blocks x 128 threads, 4 threads per code (quarter-row each).
__global__ __launch_bounds__(128) void vq_prep(const float* __restrict__ emb) {
    const int tid  = threadIdx.x;
    const int kloc = tid >> 2;
    const int part = tid & 3;
    const int k    = blockIdx.x * 32 + kloc;
    const int t    = k >> 6;                 // 64-code tiles
    const int row  = k & 63;
    const float4* er = (const float4*)(emb + k * 64) + part * 4;
    unsigned char* bp = g_b16[t];
    float s0 = 0.f, s1 = 0.f, s2 = 0.f, s3 = 0.f;
    #pragma unroll
    for (int i = 0; i < 4; i++) {
        float4 v = er[i];
        s0 = __fmaf_rn(v.x, v.x, s0);
        s1 = __fmaf_rn(v.y, v.y, s1);
        s2 = __fmaf_rn(v.z, v.z, s2);
        s3 = __fmaf_rn(v.w, v.w, s3);
        __half h0 = __float2half_rn(-v.x), h1 = __float2half_rn(-v.y);
        __half h2 = __float2half_rn(-v.z), h3 = __float2half_rn(-v.w);
        uint32_t p0 = ((uint32_t)__half_as_ushort(h1) << 16) | __half_as_ushort(h0);
        uint32_t p1 = ((uint32_t)__half_as_ushort(h3) << 16) | __half_as_ushort(h2);
        const int ii = part * 4 + i;
        uint32_t o0 = (uint32_t)(row * 128 + (4 * ii) * 2);
        uint32_t o1 = (uint32_t)(row * 128 + (4 * ii + 2) * 2);
        o0 = o0 ^ ((o0 >> 3) & 0x70);
        o1 = o1 ^ ((o1 >> 3) & 0x70);
        *(uint32_t*)(bp + o0) = p0;
        *(uint32_t*)(bp + o1) = p1;
    }
    float s = __fadd_rn(__fadd_rn(s0, s1), __fadd_rn(s2, s3));
    s += __shfl_xor_sync(0xffffffffu, s, 1);
    s += __shfl_xor_sync(0xffffffffu, s, 2);
    if (part == 0) g_c2h[k] = 0.5f * s;
}

// --- Kernel 1: fp16 MMA search, top-3 candidates per pixel ------------------
// acc seeded with 0.5*c2, codebook negated => acc = 0.5*c2 - dot = key.
// 64-code tiles as 2x32-code quarters; acc[8][4]=32 regs -> 6 CTAs/SM.
__global__ __launch_bounds__(BLKPIX, 6) void vq_main(const float* __restrict__ in) {
    extern __shared__ char sm[];
    const uint32_t sb = s2u(sm);
    const int tid  = threadIdx.x;
    const int lane = tid & 31;
    const int q    = lane >> 2;
    const int qp   = lane & 3;
    const int wrow = (tid >> 5) * 32;

    // stage c2h into smem
    {
        float4* sc2 = (float4*)(sm + SM_C2H);
        const float4* gc2 = (const float4*)g_c2h;
        sc2[tid] = gc2[tid];
        sc2[tid + BLKPIX] = gc2[tid + BLKPIX];
    }
    // load x -> fp16 A tile (SW128)
    const int p0 = blockIdx.x * BLKPIX + tid;
    const int b0 = p0 >> 12, h0i = (p0 >> 6) & 63, w0 = p0 & 63;
    const float* xin = in + ((b0 * 64) * 64 + h0i) * 64 + w0;
    #pragma unroll
    for (int c = 0; c < 64; c += 2) {
        float f0 = xin[c * HWv], f1 = xin[(c + 1) * HWv];
        __half h0 = __float2half_rn(f0), h1 = __float2half_rn(f1);
        uint32_t ph = ((uint32_t)__half_as_ushort(h1) << 16) | __half_as_ushort(h0);
        uint32_t off = (uint32_t)(tid * 128 + c * 2);
        off = off ^ ((off >> 3) & 0x70);
        *(uint32_t*)(sm + SM_A + off) = ph;
    }
    // prefetch B tile 0 (8KB: 64B per thread)
    #pragma unroll
    for (int j = 0; j < 4; j++)
        cp16(sb + SM_B0 + tid * 64 + j * 16, g_b16[0] + tid * 64 + j * 16);
    asm volatile("cp.async.commit_group;" ::: "memory");

    // Precompute per-thread swizzled address pieces.
    const int arow0 = wrow + (lane & 15);
    const uint32_t aswz0 = (uint32_t)((arow0 & 7) << 4);
    const uint32_t aswz1 = (uint32_t)(((arow0 + 16) & 7) << 4);
    const uint32_t abase0 = sb + SM_A + (uint32_t)(arow0 * 128);
    const uint32_t abase1 = sb + SM_A + (uint32_t)((arow0 + 16) * 128);
    const int brow = (lane & 7) + ((lane >> 4) << 3);
    const uint32_t bswz = (uint32_t)((brow & 7) << 4);
    const uint32_t bkhi = (uint32_t)(((lane >> 3) & 1) * 16);
    const uint32_t browoff = (uint32_t)(brow * 128);
    const int akhi = (lane >> 4) << 4;

    unsigned t1[4] = {0,0,0,0}, t2[4] = {0,0,0,0};

    for (int t = 0; t < NTILES; t++) {
        const uint32_t bB = sb + ((t & 1) ? SM_B1 : SM_B0);
        // wait for tile t data, then one sync: publishes tile t AND proves
        // everyone is done reading buffer (t+1)&1 (consumed during iter t-1)
        asm volatile("cp.async.wait_group 0;" ::: "memory");
        __syncthreads();
        if (t < NTILES - 1) {
            const uint32_t bN = sb + ((t & 1) ? SM_B0 : SM_B1);
            #pragma unroll
            for (int j = 0; j < 4; j++)
                cp16(bN + tid * 64 + j * 16, g_b16[t + 1] + tid * 64 + j * 16);
            asm volatile("cp.async.commit_group;" ::: "memory");
        }

        #pragma unroll
        for (int q2 = 0; q2 < 2; q2++) {
            const float* c2b = (const float*)(sm + SM_C2H) + t * 64 + q2 * 32 + qp * 2;
            // seed accumulators with 0.5*c2 of their code pair
            float acc[8][4];
            #pragma unroll
            for (int cf = 0; cf < 4; cf++) {
                float2 cc = *(const float2*)(c2b + cf * 8);
                acc[cf*2+0][0] = cc.x; acc[cf*2+0][1] = cc.y;
                acc[cf*2+0][2] = cc.x; acc[cf*2+0][3] = cc.y;
                acc[cf*2+1][0] = cc.x; acc[cf*2+1][1] = cc.y;
                acc[cf*2+1][2] = cc.x; acc[cf*2+1][3] = cc.y;
            }
            const uint32_t bbase = bB + (uint32_t)(q2 * 4096) + browoff;
            #pragma unroll
            for (int ks = 0; ks < 4; ks++) {
                const uint32_t akb = (uint32_t)(ks * 32) + (uint32_t)akhi;
                uint32_t A0[4], A1[4], Bx[8];
                LDSM4(A0, abase0 + (akb ^ aswz0));
                LDSM4(A1, abase1 + (akb ^ aswz1));
                const uint32_t bk = ((uint32_t)(ks * 32) + bkhi) ^ bswz;
                LDSM4(Bx,     bbase + bk);
                LDSM4(Bx + 4, bbase + 2048 + bk);
                MMAH(acc[0], A0, Bx + 0); MMAH(acc[1], A1, Bx + 0);
                MMAH(acc[2], A0, Bx + 2); MMAH(acc[3], A1, Bx + 2);
                MMAH(acc[4], A0, Bx + 4); MMAH(acc[5], A1, Bx + 4);
                MMAH(acc[6], A0, Bx + 6); MMAH(acc[7], A1, Bx + 6);
            }
            // reduce: acc IS the key; top-2 per (lane, slot), unsigned-max on raw bits
            const unsigned ccb = 1023u - (unsigned)(t * 64 + q2 * 32 + qp * 2);
            #pragma unroll
            for (int cf = 0; cf < 4; cf++) {
                unsigned i0 = ccb - (unsigned)(cf * 8);
                unsigned i1 = i0 - 1u;
                #pragma unroll
                for (int r = 0; r < 2; r++) {
                    #pragma unroll
                    for (int i = 0; i < 4; i++) {
                        unsigned km = (__float_as_uint(acc[cf*2+r][i]) & 0xFFFFFC00u)
                                      | ((i & 1) ? i1 : i0);
                        const int s = r * 2 + (i >> 1);
                        unsigned m1 = uminu(t1[s], km);
                        t1[s] = umaxu(t1[s], km);
                        t2[s] = umaxu(t2[s], m1);
                    }
                }
            }
        }
    }

    // merge the 4 quad-lanes' top-2 -> exact union top-3 per pixel
    unsigned t3[4] = {0,0,0,0};
    #pragma unroll
    for (int s = 0; s < 4; s++) {
        #pragma unroll
        for (int mk = 1; mk <= 2; mk <<= 1) {
            unsigned r1 = __shfl_xor_sync(0xffffffffu, t1[s], mk);
            unsigned r2 = __shfl_xor_sync(0xffffffffu, t2[s], mk);
            unsigned r3 = __shfl_xor_sync(0xffffffffu, t3[s], mk);
            unsigned x1 = umaxu(t1[s], r1), y1 = uminu(t1[s], r1);
            unsigned x2 = umaxu(t2[s], r2);
            t1[s] = x1;
            unsigned top2 = umaxu(y1, x2);
            t3[s] = umaxu(uminu(y1, x2), umaxu(t3[s], r3));
            t2[s] = top2;
        }
    }
    unsigned f1 = t1[0], f2 = t2[0], f3 = t3[0];
    if (qp == 1) { f1 = t1[1]; f2 = t2[1]; f3 = t3[1]; }
    if (qp == 2) { f1 = t1[2]; f2 = t2[2]; f3 = t3[2]; }
    if (qp == 3) { f1 = t1[3]; f2 = t2[3]; f3 = t3[3]; }

    const int p = blockIdx.x * BLKPIX + wrow + q + qp * 8;
    const unsigned k1 = 1023u - (f1 & 1023u);
    const unsigned k2 = 1023u - (f2 & 1023u);
    const unsigned k3 = 1023u - (f3 & 1023u);
    g_cand[p] = k1 | (k2 << 10) | (k3 << 20);
}

// Exact fp32 distance, replicating the verified 0-flip summation structure.
static __device__ __forceinline__ float exact_dist(const float* x, const float* __restrict__ e,
                                                   float sx) {
    const float4* e4 = (const float4*)e;
    float cc0=0,cc1=0,cc2=0,cc3=0,cc4=0,cc5=0,cc6=0,cc7=0;
    float s0=0,s1=0,s2=0,s3=0;
    #pragma unroll
    for (int i = 0; i < 16; i++) {
        float4 v = e4[i];
        s0 = __fmaf_rn(v.x, v.x, s0);
        s1 = __fmaf_rn(v.y, v.y, s1);
        s2 = __fmaf_rn(v.z, v.z, s2);
        s3 = __fmaf_rn(v.w, v.w, s3);
        float x0 = x[4*i], x1 = x[4*i+1], x2 = x[4*i+2], x3 = x[4*i+3];
        if ((i & 1) == 0) {
            cc0 = __fmaf_rn(x0, v.x, cc0); cc1 = __fmaf_rn(x1, v.y, cc1);
            cc2 = __fmaf_rn(x2, v.z, cc2); cc3 = __fmaf_rn(x3, v.w, cc3);
        } else {
            cc4 = __fmaf_rn(x0, v.x, cc4); cc5 = __fmaf_rn(x1, v.y, cc5);
            cc6 = __fmaf_rn(x2, v.z, cc6); cc7 = __fmaf_rn(x3, v.w, cc7);
        }
    }
    float c2 = __fadd_rn(__fadd_rn(s0, s1), __fadd_rn(s2, s3));
    float lo = __fadd_rn(__fadd_rn(cc0, cc2), __fadd_rn(cc4, cc6));
    float hi = __fadd_rn(__fadd_rn(cc1, cc3), __fadd_rn(cc5, cc7));
    float dot = __fadd_rn(lo, hi);
    return __fsub_rn(__fadd_rn(sx, c2), __fmul_rn(2.0f, dot));
}

// --- Kernel 2: exact rescore of 3 candidates, output + loss -----------------
__global__ __launch_bounds__(RBLK) void vq_rescore(const float* __restrict__ in,
                                                   const float* __restrict__ emb,
                                                   float* __restrict__ out,
                                                   int out_size) {
    const int tid = threadIdx.x;
    const int p = blockIdx.x * RBLK + tid;
    const int b = p >> 12, h = (p >> 6) & 63, w = p & 63;
    const unsigned cand = g_cand[p];
    const int k1 = (int)(cand & 1023u);
    const int k2 = (int)((cand >> 10) & 1023u);
    const int k3 = (int)((cand >> 20) & 1023u);

    const float* xg = in + ((b * 64) * 64 + h) * 64 + w;
    float x_[64];
    #pragma unroll
    for (int c = 0; c < 64; c++) x_[c] = xg[c * HWv];
    float s0 = 0.f, s1 = 0.f, s2 = 0.f, s3 = 0.f;
    #pragma unroll
    for (int i = 0; i < 32; i++) {
        float f0v = x_[2*i], f1v = x_[2*i + 1];
        if (i & 1) { s1 = __fmaf_rn(f0v, f0v, s1); s3 = __fmaf_rn(f1v, f1v, s3); }
        else       { s0 = __fmaf_rn(f0v, f0v, s0); s2 = __fmaf_rn(f1v, f1v, s2); }
    }
    const float sx = __fadd_rn(__fadd_rn(s0, s1), __fadd_rn(s2, s3));
    const float d1 = exact_dist(x_, emb + k1 * 64, sx);
    const float d2 = exact_dist(x_, emb + k2 * 64, sx);
    const float d3 = exact_dist(x_, emb + k3 * 64, sx);
    float db = d1; int kwin = k1;
    if (d2 < db || (d2 == db && k2 < kwin)) { db = d2; kwin = k2; }
    if (d3 < db || (d3 == db && k3 < kwin)) { db = d3; kwin = k3; }

    const float4* eb = (const float4*)(emb + kwin * 64);
    float* op = out + ((b * 64) * 64 + h) * 64 + w;
    float ls = 0.f;
    #pragma unroll
    for (int i = 0; i < 16; i++) {
        float4 qv = eb[i];
        op[(4*i + 0) * HWv] = qv.x;
        op[(4*i + 1) * HWv] = qv.y;
        op[(4*i + 2) * HWv] = qv.z;
        op[(4*i + 3) * HWv] = qv.w;
        float e0 = qv.x - x_[4*i],   e1 = qv.y - x_[4*i+1];
        float e2 = qv.z - x_[4*i+2], e3 = qv.w - x_[4*i+3];
        ls += e0*e0 + e1*e1 + e2*e2 + e3*e3;
    }
    #pragma unroll
    for (int off = 16; off; off >>= 1)
        ls += __shfl_xor_sync(0xffffffffu, ls, off);
    if ((tid & 31) == 0) atomicAdd(&g_loss, ls);

    __syncthreads();
    if (tid == 0) {
        __threadfence();
        unsigned v = atomicAdd(&g_count, 1u);
        if (v == RGRID - 1) {
            __threadfence();
            if (out_size > NUMELv)
                out[NUMELv] = 1.25f * g_loss / (float)NUMELv;
            g_loss = 0.f;
            g_count = 0u;
        }
    }
}

extern "C" void kernel_launch(void* const* d_in, const int* in_sizes, int n_in,
                              void* d_out, int out_size) {
    const float* in  = (const float*)d_in[0];
    const float* emb = (const float*)d_in[1];
    float* out = (float*)d_out;

    vq_prep<<<32, 128>>>(emb);
    cudaFuncSetAttribute(vq_main, cudaFuncAttributeMaxDynamicSharedMemorySize, SM_TOTAL);
    vq_main<<<GRIDv, BLKPIX, SM_TOTAL>>>(in);
    vq_rescore<<<RGRID, RBLK>>>(in, emb, out, out_size);
}